// round 3
// baseline (speedup 1.0000x reference)
#include <cuda_runtime.h>
#include <math.h>

#define B_   8
#define N_   2000
#define T_   8
#define F_   128
#define DEG_ 8
#define H_   4
#define D1_  64
#define D2_  64
#define G_   64
#define PW_  16
#define BT_  (B_*T_)     // 64
#define SEQ_ (N_*T_)     // 16000
#define HD_  (H_*D1_)    // 256

// -------- scratch (static device allocations are the sanctioned scratch path) --------
__device__ float g_z1  [(size_t)BT_*N_*HD_];     // 131 MB
__device__ float g_h1  [(size_t)BT_*N_*HD_];     // 131 MB
__device__ float g_z2  [(size_t)BT_*N_*D2_];     // 33 MB
__device__ float g_seqT[(size_t)SEQ_*B_*D2_];    // 33 MB  (xs layout: [s][b][d])
__device__ float g_gi  [(size_t)SEQ_*B_*3*G_];   // 98 MB  ([s][b][j])
__device__ float g_ssrc1[BT_*H_*N_];
__device__ float g_sdst1[BT_*H_*N_];
__device__ float g_ssrc2[BT_*N_];
__device__ float g_sdst2[BT_*N_];
__device__ float g_hloc[(size_t)N_*B_*G_];       // [n][b][g]
__device__ float g_W1cat[F_*HD_];                // [f][h*64+d]
__device__ float g_WihT [D2_*3*G_];              // [d][j]

// ---------------------------------------------------------------------------
// Pack W1 -> [F, H*D1] and Wih -> [D2, 3G]
__global__ void pack_kernel(const float* __restrict__ W1, const float* __restrict__ Wih)
{
    int i = blockIdx.x * 256 + threadIdx.x;
    if (i < F_*HD_) {
        int f = i / HD_, c = i % HD_;
        int h = c >> 6, d = c & 63;
        g_W1cat[i] = W1[((size_t)h*F_ + f)*D1_ + d];
    }
    if (i < D2_*3*G_) {
        int d = i / (3*G_), j = i % (3*G_);
        g_WihT[i] = Wih[(size_t)j*D2_ + d];
    }
}

// ---------------------------------------------------------------------------
// Tiled SGEMM: C[z] = A[z] (MxK) * Bm (KxN) + bias.  BM=128 BN=64 BK=16, 8x4 microtile.
__global__ void __launch_bounds__(256)
gemm_bias(const float* __restrict__ A, const float* __restrict__ Bm,
          const float* __restrict__ bias, float* __restrict__ C,
          int M, int N, int K, int lda, int ldc,
          long aOuter, long aInner, int innerCnt, long cStride)
{
    __shared__ float As[16][128];
    __shared__ float Bs[16][64];

    int z = blockIdx.z;
    const float* Ab = A + (long)(z / innerCnt) * aOuter + (long)(z % innerCnt) * aInner;
    float* Cb = C + (long)z * cStride;
    int m0 = blockIdx.x * 128;
    int n0 = blockIdx.y * 64;
    int tid = threadIdx.x;
    int tx = tid & 15;          // col group  (4 cols)
    int ty = tid >> 4;          // row group  (8 rows)

    float acc[8][4];
#pragma unroll
    for (int i = 0; i < 8; i++)
#pragma unroll
        for (int j = 0; j < 4; j++) acc[i][j] = 0.f;

    for (int k0 = 0; k0 < K; k0 += 16) {
        // A tile: 128x16, 2 float4 per thread, store transposed
#pragma unroll
        for (int q = 0; q < 2; q++) {
            int l4  = tid * 2 + q;
            int row = l4 >> 2;
            int c4  = (l4 & 3) << 2;
            int gm  = m0 + row; if (gm > M - 1) gm = M - 1;
            float4 v = *reinterpret_cast<const float4*>(Ab + (long)gm * lda + k0 + c4);
            As[c4 + 0][row] = v.x; As[c4 + 1][row] = v.y;
            As[c4 + 2][row] = v.z; As[c4 + 3][row] = v.w;
        }
        { // B tile: 16x64, 1 float4 per thread
            int row = tid >> 4;
            int c4  = (tid & 15) << 2;
            float4 v = *reinterpret_cast<const float4*>(Bm + (long)(k0 + row) * N + n0 + c4);
            *reinterpret_cast<float4*>(&Bs[row][c4]) = v;
        }
        __syncthreads();
#pragma unroll
        for (int kk = 0; kk < 16; kk++) {
            float a[8], bb[4];
#pragma unroll
            for (int i = 0; i < 8; i++) a[i] = As[kk][ty * 8 + i];
#pragma unroll
            for (int j = 0; j < 4; j++) bb[j] = Bs[kk][tx * 4 + j];
#pragma unroll
            for (int i = 0; i < 8; i++)
#pragma unroll
                for (int j = 0; j < 4; j++)
                    acc[i][j] = fmaf(a[i], bb[j], acc[i][j]);
        }
        __syncthreads();
    }

#pragma unroll
    for (int i = 0; i < 8; i++) {
        int gm = m0 + ty * 8 + i;
        if (gm < M) {
#pragma unroll
            for (int j = 0; j < 4; j++) {
                int gn = n0 + tx * 4 + j;
                Cb[(long)gm * ldc + gn] = acc[i][j] + bias[gn];
            }
        }
    }
}

// ---------------------------------------------------------------------------
// Attention scores layer 1: s_src/s_dst[bt][h][n] = z1[bt][n][h*64+:]  dot a1 parts
__global__ void scores1_kernel(const float* __restrict__ a1)
{
    int gw   = (blockIdx.x * blockDim.x + threadIdx.x) >> 5;
    int lane = threadIdx.x & 31;
    if (gw >= BT_ * N_) return;
    int bt = gw / N_, n = gw % N_;
    const float* zr = g_z1 + ((size_t)bt * N_ + n) * HD_;
#pragma unroll
    for (int h = 0; h < H_; h++) {
        float s = 0.f, d = 0.f;
#pragma unroll
        for (int q = 0; q < 2; q++) {
            int dd = lane + 32 * q;
            float zv = zr[h * 64 + dd];
            s = fmaf(zv, a1[h * 128 + dd], s);
            d = fmaf(zv, a1[h * 128 + 64 + dd], d);
        }
#pragma unroll
        for (int o = 16; o >= 1; o >>= 1) {
            s += __shfl_xor_sync(0xffffffffu, s, o);
            d += __shfl_xor_sync(0xffffffffu, d, o);
        }
        if (lane == 0) {
            g_ssrc1[(bt * H_ + h) * N_ + n] = s;
            g_sdst1[(bt * H_ + h) * N_ + n] = d;
        }
    }
}

__global__ void scores2_kernel(const float* __restrict__ a2)
{
    int gw   = (blockIdx.x * blockDim.x + threadIdx.x) >> 5;
    int lane = threadIdx.x & 31;
    if (gw >= BT_ * N_) return;
    int bt = gw / N_, n = gw % N_;
    const float* zr = g_z2 + ((size_t)bt * N_ + n) * D2_;
    float s = 0.f, d = 0.f;
#pragma unroll
    for (int q = 0; q < 2; q++) {
        int dd = lane + 32 * q;
        float zv = zr[dd];
        s = fmaf(zv, a2[dd],      s);
        d = fmaf(zv, a2[64 + dd], d);
    }
#pragma unroll
    for (int o = 16; o >= 1; o >>= 1) {
        s += __shfl_xor_sync(0xffffffffu, s, o);
        d += __shfl_xor_sync(0xffffffffu, d, o);
    }
    if (lane == 0) { g_ssrc2[bt * N_ + n] = s; g_sdst2[bt * N_ + n] = d; }
}

// ---------------------------------------------------------------------------
// GAT attention layer 1: warp per (bt,n), 4 heads, softmax over 8 neighbors, ELU
__global__ void attn1_kernel(const int* __restrict__ src, const float* __restrict__ a1b)
{
    int gw   = (blockIdx.x * blockDim.x + threadIdx.x) >> 5;
    int lane = threadIdx.x & 31;
    if (gw >= BT_ * N_) return;
    int bt = gw / N_, n = gw % N_;

    int sk = 0;
    if (lane < 8) sk = src[n * DEG_ + lane];

#pragma unroll
    for (int h = 0; h < H_; h++) {
        float sd = g_sdst1[(bt * H_ + h) * N_ + n];
        float e = -1e30f;
        if (lane < 8) {
            float v = g_ssrc1[(bt * H_ + h) * N_ + sk] + sd + a1b[h];
            e = (v > 0.f) ? v : 0.01f * v;
        }
        float m = e;
#pragma unroll
        for (int o = 4; o >= 1; o >>= 1) m = fmaxf(m, __shfl_xor_sync(0xffffffffu, m, o, 8));
        float p = __expf(e - m);
        float sum = p;
#pragma unroll
        for (int o = 4; o >= 1; o >>= 1) sum += __shfl_xor_sync(0xffffffffu, sum, o, 8);
        float alpha = p / sum;

        float acc0 = 0.f, acc1 = 0.f;
#pragma unroll
        for (int k = 0; k < 8; k++) {
            float al = __shfl_sync(0xffffffffu, alpha, k);
            int   s2 = __shfl_sync(0xffffffffu, sk, k);
            const float* zrow = g_z1 + ((size_t)bt * N_ + s2) * HD_ + h * 64;
            acc0 = fmaf(al, zrow[lane],      acc0);
            acc1 = fmaf(al, zrow[lane + 32], acc1);
        }
        size_t o = ((size_t)bt * N_ + n) * HD_ + h * 64 + lane;
        g_h1[o]      = acc0 > 0.f ? acc0 : expm1f(acc0);
        g_h1[o + 32] = acc1 > 0.f ? acc1 : expm1f(acc1);
    }
}

// GAT attention layer 2 (single head), writes directly into xs layout [s][b][d]
__global__ void attn2_kernel(const int* __restrict__ src, const float* __restrict__ a2b)
{
    int gw   = (blockIdx.x * blockDim.x + threadIdx.x) >> 5;
    int lane = threadIdx.x & 31;
    if (gw >= BT_ * N_) return;
    int bt = gw / N_, n = gw % N_;
    int b = bt / T_, t = bt % T_;

    int sk = 0;
    if (lane < 8) sk = src[n * DEG_ + lane];

    float sd = g_sdst2[bt * N_ + n];
    float e = -1e30f;
    if (lane < 8) {
        float v = g_ssrc2[bt * N_ + sk] + sd + a2b[0];
        e = (v > 0.f) ? v : 0.01f * v;
    }
    float m = e;
#pragma unroll
    for (int o = 4; o >= 1; o >>= 1) m = fmaxf(m, __shfl_xor_sync(0xffffffffu, m, o, 8));
    float p = __expf(e - m);
    float sum = p;
#pragma unroll
    for (int o = 4; o >= 1; o >>= 1) sum += __shfl_xor_sync(0xffffffffu, sum, o, 8);
    float alpha = p / sum;

    float acc0 = 0.f, acc1 = 0.f;
#pragma unroll
    for (int k = 0; k < 8; k++) {
        float al = __shfl_sync(0xffffffffu, alpha, k);
        int   s2 = __shfl_sync(0xffffffffu, sk, k);
        const float* zrow = g_z2 + ((size_t)bt * N_ + s2) * D2_;
        acc0 = fmaf(al, zrow[lane],      acc0);
        acc1 = fmaf(al, zrow[lane + 32], acc1);
    }
    int srow = (n * T_ + t) * B_ + b;
    size_t o = (size_t)srow * D2_ + lane;
    g_seqT[o]      = acc0 > 0.f ? acc0 : expm1f(acc0);
    g_seqT[o + 32] = acc1 > 0.f ? acc1 : expm1f(acc1);
}

// ---------------------------------------------------------------------------
// GRU scan: 8 blocks (one per batch chain), 384 threads.
// thread t -> (j = t>>1, half = t&1): half of the 64-wide dot for gate-unit j.
__device__ __forceinline__ float sigf(float x)  { return 1.0f / (1.0f + __expf(-x)); }
__device__ __forceinline__ float tanhfast(float x)
{
    x = fminf(fmaxf(x, -20.f), 20.f);
    float e = __expf(-2.f * x);
    return (1.f - e) / (1.f + e);
}

__global__ void __launch_bounds__(384)
gru_scan(const float* __restrict__ gi, const float* __restrict__ h0,
         const float* __restrict__ Whh, const float* __restrict__ bhh)
{
    const int b    = blockIdx.x;
    const int t    = threadIdx.x;
    const int j    = t >> 1;
    const int half = t & 1;

    float w[32];
#pragma unroll
    for (int k = 0; k < 32; k++) w[k] = Whh[(size_t)j * 64 + half * 32 + k];
    const float bj = bhh[j];

    __shared__ __align__(16) float h_sh[64];
    __shared__ float sA[192];   // gi
    __shared__ float sB[192];   // gh
    if (t < 64) h_sh[t] = h0[b * 64 + t];
    __syncthreads();

    const long stride = (long)B_ * 192;   // 1536
    const float* gp = gi + (long)b * 192 + j;
    // 3-deep prefetch pipeline (DRAM latency > per-step time)
    float q0 = 0.f, q1 = 0.f, q2 = 0.f;
    if (half == 0) {
        q0 = gp[0];
        q1 = gp[stride];
        q2 = gp[2 * stride];
    }

    for (int s = 0; s < SEQ_; s++) {
        float gcur = q0;
        q0 = q1; q1 = q2;
        if (half == 0 && s + 3 < SEQ_) q2 = __ldg(gp + (long)(s + 3) * stride);

        const float4* h4 = reinterpret_cast<const float4*>(h_sh + half * 32);
        float a0 = 0.f, a1v = 0.f, a2v = 0.f, a3 = 0.f;
#pragma unroll
        for (int k = 0; k < 8; k++) {
            float4 hv = h4[k];
            a0  = fmaf(w[4 * k + 0], hv.x, a0);
            a1v = fmaf(w[4 * k + 1], hv.y, a1v);
            a2v = fmaf(w[4 * k + 2], hv.z, a2v);
            a3  = fmaf(w[4 * k + 3], hv.w, a3);
        }
        float part = (a0 + a1v) + (a2v + a3);
        part += __shfl_xor_sync(0xffffffffu, part, 1);
        if (half == 0) { sA[j] = gcur; sB[j] = part + bj; }
        __syncthreads();

        if (half == 0 && j < 64) {
            float r  = sigf(sA[j]       + sB[j]);
            float zg = sigf(sA[64 + j]  + sB[64 + j]);
            float nn = tanhfast(sA[128 + j] + r * sB[128 + j]);
            float ho = h_sh[j];
            float hn = fmaf(zg, ho - nn, nn);   // (1-zg)*nn + zg*h
            h_sh[j] = hn;
            if ((s & 7) == 7)
                g_hloc[((size_t)(s >> 3) * B_ + b) * G_ + j] = hn;
        }
        __syncthreads();
    }
}

// ---------------------------------------------------------------------------
// Output projection: out[b][n][p] = h_loc[n][b][:] . Wp[:,p] + bp[p]
__global__ void proj_kernel(const float* __restrict__ Wp, const float* __restrict__ bp,
                            float* __restrict__ out)
{
    int gw   = (blockIdx.x * blockDim.x + threadIdx.x) >> 5;
    int lane = threadIdx.x & 31;
    if (gw >= B_ * N_) return;
    int b = gw / N_, n = gw % N_;
    if (lane < PW_) {
        const float* hl = g_hloc + ((size_t)n * B_ + b) * G_;
        float acc = bp[lane];
#pragma unroll
        for (int g = 0; g < G_; g++) acc = fmaf(hl[g], Wp[g * PW_ + lane], acc);
        out[((size_t)b * N_ + n) * PW_ + lane] = acc;
    }
}

// ---------------------------------------------------------------------------
extern "C" void kernel_launch(void* const* d_in, const int* in_sizes, int n_in,
                              void* d_out, int out_size)
{
    const float* dynamic = (const float*)d_in[0];
    const float* h0      = (const float*)d_in[1];
    const int*   src     = (const int*)  d_in[2];
    const float* W1      = (const float*)d_in[3];
    const float* b1      = (const float*)d_in[4];
    const float* a1      = (const float*)d_in[5];
    const float* a1b     = (const float*)d_in[6];
    const float* W2      = (const float*)d_in[7];
    const float* b2      = (const float*)d_in[8];
    const float* a2      = (const float*)d_in[9];
    const float* a2b     = (const float*)d_in[10];
    const float* Wih     = (const float*)d_in[11];
    const float* Whh     = (const float*)d_in[12];
    const float* bih     = (const float*)d_in[13];
    const float* bhh     = (const float*)d_in[14];
    const float* Wp      = (const float*)d_in[15];
    const float* bp      = (const float*)d_in[16];
    float* out = (float*)d_out;

    float *z1p, *h1p, *z2p, *seqTp, *gip, *W1catp, *WihTp;
    cudaGetSymbolAddress((void**)&z1p,    g_z1);
    cudaGetSymbolAddress((void**)&h1p,    g_h1);
    cudaGetSymbolAddress((void**)&z2p,    g_z2);
    cudaGetSymbolAddress((void**)&seqTp,  g_seqT);
    cudaGetSymbolAddress((void**)&gip,    g_gi);
    cudaGetSymbolAddress((void**)&W1catp, g_W1cat);
    cudaGetSymbolAddress((void**)&WihTp,  g_WihT);

    // 0) pack weights
    pack_kernel<<<128, 256>>>(W1, Wih);

    // 1) z1 = x @ W1cat + b1   (per (b,t): 2000x128 @ 128x256)
    gemm_bias<<<dim3(16, 4, BT_), 256>>>(dynamic, W1catp, b1, z1p,
                                         N_, HD_, F_, T_ * F_, HD_,
                                         (long)N_ * T_ * F_, (long)F_, T_,
                                         (long)N_ * HD_);
    // 2) attention scores + aggregation layer 1 -> h1 (ELU)
    scores1_kernel<<<16000, 256>>>(a1);
    attn1_kernel<<<16000, 256>>>(src, a1b);

    // 3) z2 = h1 @ W2 + b2   (per (b,t): 2000x256 @ 256x64)
    gemm_bias<<<dim3(16, 1, BT_), 256>>>(h1p, W2, b2, z2p,
                                         N_, D2_, HD_, HD_, D2_,
                                         (long)N_ * HD_, 0L, 1,
                                         (long)N_ * D2_);
    // 4) attention layer 2 -> seqT (xs layout), ELU
    scores2_kernel<<<16000, 256>>>(a2);
    attn2_kernel<<<16000, 256>>>(src, a2b);

    // 5) gi = seqT @ WihT + bih   (128000x64 @ 64x192)
    gemm_bias<<<dim3(1000, 3, 1), 256>>>(seqTp, WihTp, bih, gip,
                                         SEQ_ * B_, 3 * G_, D2_, D2_, 3 * G_,
                                         0L, 0L, 1, 0L);

    // 6) sequential GRU scan (8 independent chains)
    gru_scan<<<B_, 384>>>(gip, h0, Whh, bhh);

    // 7) projection
    proj_kernel<<<2000, 256>>>(Wp, bp, out);
}

// round 4
// speedup vs baseline: 1.6402x; 1.6402x over previous
#include <cuda_runtime.h>
#include <math.h>

#define B_   8
#define N_   2000
#define T_   8
#define F_   128
#define DEG_ 8
#define H_   4
#define D1_  64
#define D2_  64
#define G_   64
#define PW_  16
#define BT_  (B_*T_)     // 64
#define SEQ_ (N_*T_)     // 16000
#define HD_  (H_*D1_)    // 256

// -------- scratch (static device arrays are the sanctioned scratch path) --------
__device__ float g_z1  [(size_t)BT_*N_*HD_];     // 131 MB
__device__ float g_h1  [(size_t)BT_*N_*HD_];     // 131 MB
__device__ float g_z2  [(size_t)BT_*N_*D2_];     // 33 MB
__device__ float g_seqT[(size_t)SEQ_*B_*D2_];    // 33 MB  (xs layout: [s][b][d])
__device__ float g_gi  [(size_t)SEQ_*B_*3*G_];   // 98 MB  ([s][b][j])
__device__ float g_ssrc1[BT_*H_*N_];
__device__ float g_sdst1[BT_*H_*N_];
__device__ float g_ssrc2[BT_*N_];
__device__ float g_sdst2[BT_*N_];
__device__ float g_hloc[(size_t)N_*B_*G_];       // [n][b][g]
__device__ float g_W1cat[F_*HD_];                // [f][h*64+d]
__device__ float g_WihT [D2_*3*G_];              // [d][j]

// ---------------------------------------------------------------------------
// f32x2 packed helpers (sm_103a: FFMA2 only reachable via PTX)
__device__ __forceinline__ unsigned long long ffma2_(unsigned long long a,
                                                     unsigned long long b,
                                                     unsigned long long c)
{
    unsigned long long d;
    asm("fma.rn.f32x2 %0, %1, %2, %3;" : "=l"(d) : "l"(a), "l"(b), "l"(c));
    return d;
}
__device__ __forceinline__ unsigned long long fadd2_(unsigned long long a,
                                                     unsigned long long b)
{
    unsigned long long d;
    asm("add.rn.f32x2 %0, %1, %2;" : "=l"(d) : "l"(a), "l"(b));
    return d;
}
__device__ __forceinline__ unsigned long long pack2_(float x, float y)
{
    unsigned long long p;
    asm("mov.b64 %0, {%1, %2};" : "=l"(p) : "f"(x), "f"(y));
    return p;
}
__device__ __forceinline__ float unpack_sum_(unsigned long long s)
{
    float lo, hi;
    asm("mov.b64 {%0, %1}, %2;" : "=f"(lo), "=f"(hi) : "l"(s));
    return lo + hi;
}

// ---------------------------------------------------------------------------
// Pack W1 -> [F, H*D1] and Wih -> [D2, 3G]
__global__ void pack_kernel(const float* __restrict__ W1, const float* __restrict__ Wih)
{
    int i = blockIdx.x * 256 + threadIdx.x;
    if (i < F_*HD_) {
        int f = i / HD_, c = i % HD_;
        int h = c >> 6, d = c & 63;
        g_W1cat[i] = W1[((size_t)h*F_ + f)*D1_ + d];
    }
    if (i < D2_*3*G_) {
        int d = i / (3*G_), j = i % (3*G_);
        g_WihT[i] = Wih[(size_t)j*D2_ + d];
    }
}

// ---------------------------------------------------------------------------
// Tiled SGEMM: C[z] = A[z] (MxK) * Bm (KxN) + bias.  BM=128 BN=64 BK=16, 8x4 microtile.
__global__ void __launch_bounds__(256)
gemm_bias(const float* __restrict__ A, const float* __restrict__ Bm,
          const float* __restrict__ bias, float* __restrict__ C,
          int M, int N, int K, int lda, int ldc,
          long aOuter, long aInner, int innerCnt, long cStride)
{
    __shared__ float As[16][128];
    __shared__ float Bs[16][64];

    int z = blockIdx.z;
    const float* Ab = A + (long)(z / innerCnt) * aOuter + (long)(z % innerCnt) * aInner;
    float* Cb = C + (long)z * cStride;
    int m0 = blockIdx.x * 128;
    int n0 = blockIdx.y * 64;
    int tid = threadIdx.x;
    int tx = tid & 15;          // col group  (4 cols)
    int ty = tid >> 4;          // row group  (8 rows)

    float acc[8][4];
#pragma unroll
    for (int i = 0; i < 8; i++)
#pragma unroll
        for (int j = 0; j < 4; j++) acc[i][j] = 0.f;

    for (int k0 = 0; k0 < K; k0 += 16) {
        // A tile: 128x16, 2 float4 per thread, store transposed
#pragma unroll
        for (int q = 0; q < 2; q++) {
            int l4  = tid * 2 + q;
            int row = l4 >> 2;
            int c4  = (l4 & 3) << 2;
            int gm  = m0 + row; if (gm > M - 1) gm = M - 1;
            float4 v = *reinterpret_cast<const float4*>(Ab + (long)gm * lda + k0 + c4);
            As[c4 + 0][row] = v.x; As[c4 + 1][row] = v.y;
            As[c4 + 2][row] = v.z; As[c4 + 3][row] = v.w;
        }
        { // B tile: 16x64, 1 float4 per thread
            int row = tid >> 4;
            int c4  = (tid & 15) << 2;
            float4 v = *reinterpret_cast<const float4*>(Bm + (long)(k0 + row) * N + n0 + c4);
            *reinterpret_cast<float4*>(&Bs[row][c4]) = v;
        }
        __syncthreads();
#pragma unroll
        for (int kk = 0; kk < 16; kk++) {
            float a[8], bb[4];
#pragma unroll
            for (int i = 0; i < 8; i++) a[i] = As[kk][ty * 8 + i];
#pragma unroll
            for (int j = 0; j < 4; j++) bb[j] = Bs[kk][tx * 4 + j];
#pragma unroll
            for (int i = 0; i < 8; i++)
#pragma unroll
                for (int j = 0; j < 4; j++)
                    acc[i][j] = fmaf(a[i], bb[j], acc[i][j]);
        }
        __syncthreads();
    }

#pragma unroll
    for (int i = 0; i < 8; i++) {
        int gm = m0 + ty * 8 + i;
        if (gm < M) {
#pragma unroll
            for (int j = 0; j < 4; j++) {
                int gn = n0 + tx * 4 + j;
                Cb[(long)gm * ldc + gn] = acc[i][j] + bias[gn];
            }
        }
    }
}

// ---------------------------------------------------------------------------
// Attention scores layer 1
__global__ void scores1_kernel(const float* __restrict__ a1)
{
    int gw   = (blockIdx.x * blockDim.x + threadIdx.x) >> 5;
    int lane = threadIdx.x & 31;
    if (gw >= BT_ * N_) return;
    int bt = gw / N_, n = gw % N_;
    const float* zr = g_z1 + ((size_t)bt * N_ + n) * HD_;
#pragma unroll
    for (int h = 0; h < H_; h++) {
        float s = 0.f, d = 0.f;
#pragma unroll
        for (int q = 0; q < 2; q++) {
            int dd = lane + 32 * q;
            float zv = zr[h * 64 + dd];
            s = fmaf(zv, a1[h * 128 + dd], s);
            d = fmaf(zv, a1[h * 128 + 64 + dd], d);
        }
#pragma unroll
        for (int o = 16; o >= 1; o >>= 1) {
            s += __shfl_xor_sync(0xffffffffu, s, o);
            d += __shfl_xor_sync(0xffffffffu, d, o);
        }
        if (lane == 0) {
            g_ssrc1[(bt * H_ + h) * N_ + n] = s;
            g_sdst1[(bt * H_ + h) * N_ + n] = d;
        }
    }
}

__global__ void scores2_kernel(const float* __restrict__ a2)
{
    int gw   = (blockIdx.x * blockDim.x + threadIdx.x) >> 5;
    int lane = threadIdx.x & 31;
    if (gw >= BT_ * N_) return;
    int bt = gw / N_, n = gw % N_;
    const float* zr = g_z2 + ((size_t)bt * N_ + n) * D2_;
    float s = 0.f, d = 0.f;
#pragma unroll
    for (int q = 0; q < 2; q++) {
        int dd = lane + 32 * q;
        float zv = zr[dd];
        s = fmaf(zv, a2[dd],      s);
        d = fmaf(zv, a2[64 + dd], d);
    }
#pragma unroll
    for (int o = 16; o >= 1; o >>= 1) {
        s += __shfl_xor_sync(0xffffffffu, s, o);
        d += __shfl_xor_sync(0xffffffffu, d, o);
    }
    if (lane == 0) { g_ssrc2[bt * N_ + n] = s; g_sdst2[bt * N_ + n] = d; }
}

// ---------------------------------------------------------------------------
// GAT attention layer 1: warp per (bt,n), 4 heads, softmax over 8 neighbors, ELU
__global__ void attn1_kernel(const int* __restrict__ src, const float* __restrict__ a1b)
{
    int gw   = (blockIdx.x * blockDim.x + threadIdx.x) >> 5;
    int lane = threadIdx.x & 31;
    if (gw >= BT_ * N_) return;
    int bt = gw / N_, n = gw % N_;

    int sk = 0;
    if (lane < 8) sk = src[n * DEG_ + lane];

#pragma unroll
    for (int h = 0; h < H_; h++) {
        float sd = g_sdst1[(bt * H_ + h) * N_ + n];
        float e = -1e30f;
        if (lane < 8) {
            float v = g_ssrc1[(bt * H_ + h) * N_ + sk] + sd + a1b[h];
            e = (v > 0.f) ? v : 0.01f * v;
        }
        float m = e;
#pragma unroll
        for (int o = 4; o >= 1; o >>= 1) m = fmaxf(m, __shfl_xor_sync(0xffffffffu, m, o, 8));
        float p = __expf(e - m);
        float sum = p;
#pragma unroll
        for (int o = 4; o >= 1; o >>= 1) sum += __shfl_xor_sync(0xffffffffu, sum, o, 8);
        float alpha = p / sum;

        float acc0 = 0.f, acc1 = 0.f;
#pragma unroll
        for (int k = 0; k < 8; k++) {
            float al = __shfl_sync(0xffffffffu, alpha, k);
            int   s2 = __shfl_sync(0xffffffffu, sk, k);
            const float* zrow = g_z1 + ((size_t)bt * N_ + s2) * HD_ + h * 64;
            acc0 = fmaf(al, zrow[lane],      acc0);
            acc1 = fmaf(al, zrow[lane + 32], acc1);
        }
        size_t o = ((size_t)bt * N_ + n) * HD_ + h * 64 + lane;
        g_h1[o]      = acc0 > 0.f ? acc0 : expm1f(acc0);
        g_h1[o + 32] = acc1 > 0.f ? acc1 : expm1f(acc1);
    }
}

// GAT attention layer 2 (single head), writes directly into xs layout [s][b][d]
__global__ void attn2_kernel(const int* __restrict__ src, const float* __restrict__ a2b)
{
    int gw   = (blockIdx.x * blockDim.x + threadIdx.x) >> 5;
    int lane = threadIdx.x & 31;
    if (gw >= BT_ * N_) return;
    int bt = gw / N_, n = gw % N_;
    int b = bt / T_, t = bt % T_;

    int sk = 0;
    if (lane < 8) sk = src[n * DEG_ + lane];

    float sd = g_sdst2[bt * N_ + n];
    float e = -1e30f;
    if (lane < 8) {
        float v = g_ssrc2[bt * N_ + sk] + sd + a2b[0];
        e = (v > 0.f) ? v : 0.01f * v;
    }
    float m = e;
#pragma unroll
    for (int o = 4; o >= 1; o >>= 1) m = fmaxf(m, __shfl_xor_sync(0xffffffffu, m, o, 8));
    float p = __expf(e - m);
    float sum = p;
#pragma unroll
    for (int o = 4; o >= 1; o >>= 1) sum += __shfl_xor_sync(0xffffffffu, sum, o, 8);
    float alpha = p / sum;

    float acc0 = 0.f, acc1 = 0.f;
#pragma unroll
    for (int k = 0; k < 8; k++) {
        float al = __shfl_sync(0xffffffffu, alpha, k);
        int   s2 = __shfl_sync(0xffffffffu, sk, k);
        const float* zrow = g_z2 + ((size_t)bt * N_ + s2) * D2_;
        acc0 = fmaf(al, zrow[lane],      acc0);
        acc1 = fmaf(al, zrow[lane + 32], acc1);
    }
    int srow = (n * T_ + t) * B_ + b;
    size_t o = (size_t)srow * D2_ + lane;
    g_seqT[o]      = acc0 > 0.f ? acc0 : expm1f(acc0);
    g_seqT[o + 32] = acc1 > 0.f ? acc1 : expm1f(acc1);
}

// ---------------------------------------------------------------------------
// GRU scan v2: 8 blocks (one per chain), 256 threads (8 warps).
// Warp w owns units u = w*8+m.  Lane l = g*8+m computes the FULL 64-wide dot
// for gate g of unit u.  All 3 gates of a unit sit in one warp -> 4 shfls, no
// smem exchange, ONE __syncthreads per step (double-buffered h).
__global__ void __launch_bounds__(256, 1)
gru_scan(const float* __restrict__ gi, const float* __restrict__ h0,
         const float* __restrict__ Whh, const float* __restrict__ bhh)
{
    const int b   = blockIdx.x;
    const int tid = threadIdx.x;
    const int w   = tid >> 5;
    const int l   = tid & 31;
    const int m   = l & 7;
    const int g   = (l < 24) ? (l >> 3) : 0;   // idle lanes alias gate 0 (harmless)
    const int u   = w * 8 + m;
    const int j   = g * 64 + u;                // row in [0,192)
    const bool writer = (l < 8);

    // Whh row j packed into 32 f32x2 registers
    unsigned long long wp[32];
    {
        const float* wr = Whh + (size_t)j * 64;
#pragma unroll
        for (int k = 0; k < 32; k++) wp[k] = pack2_(wr[2 * k], wr[2 * k + 1]);
    }
    const float bj = bhh[j];

    __shared__ __align__(16) float h_sh[2][64];
    if (tid < 64) h_sh[0][tid] = h0[b * 64 + tid];
    __syncthreads();

    const long STRIDE = (long)B_ * 192;        // 1536 floats/step
    const float* gp = gi + (long)b * 192 + j;

    float q[4];
#pragma unroll
    for (int i = 0; i < 4; i++) q[i] = __ldg(gp + (long)i * STRIDE);

    for (int s = 0; s < SEQ_; s += 4) {
#pragma unroll
        for (int i = 0; i < 4; i++) {
            // refill prefetch slot early (DRAM latency spans ~3 steps)
            float qn = 0.f;
            if (s + i + 4 < SEQ_) qn = __ldg(gp + (long)(s + i + 4) * STRIDE);

            const int p = i & 1;               // read parity (buf0 holds state for even steps)
            const float* hr = h_sh[p];
            float* hw = h_sh[1 - p];

            // full 64-wide dot in f32x2
            const ulonglong2* h2 = reinterpret_cast<const ulonglong2*>(hr);
            unsigned long long a0 = 0ull, a1 = 0ull, a2 = 0ull, a3 = 0ull;
#pragma unroll
            for (int k = 0; k < 8; k++) {
                ulonglong2 hv0 = h2[2 * k];
                ulonglong2 hv1 = h2[2 * k + 1];
                a0 = ffma2_(wp[4 * k + 0], hv0.x, a0);
                a1 = ffma2_(wp[4 * k + 1], hv0.y, a1);
                a2 = ffma2_(wp[4 * k + 2], hv1.x, a2);
                a3 = ffma2_(wp[4 * k + 3], hv1.y, a3);
            }
            float gh = unpack_sum_(fadd2_(fadd2_(a0, a1), fadd2_(a2, a3)));

            float A  = q[i];                   // gi_j (incl. bih)
            float Bv = gh + bj;                // gh_j + bhh_j
            float srz = A + Bv;

            const unsigned msk = 0xffffffffu;
            float r_in = __shfl_sync(msk, srz, m);
            float z_in = __shfl_sync(msk, srz, 8 + m);
            float nA   = __shfl_sync(msk, A,  16 + m);
            float nB   = __shfl_sync(msk, Bv, 16 + m);

            float r  = __fdividef(1.f, 1.f + __expf(-r_in));
            float zg = __fdividef(1.f, 1.f + __expf(-z_in));
            float narg = fmaf(r, nB, nA);
            narg = fminf(fmaxf(narg, -15.f), 15.f);
            float e  = __expf(-2.f * narg);
            float nn = __fdividef(1.f - e, 1.f + e);
            float h_u = hr[u];
            float hn = fmaf(zg, h_u - nn, nn); // (1-zg)*nn + zg*h

            if (writer) {
                hw[u] = hn;
                if (i == 3 && ((s & 7) == 4))  // step s+3 has (s+3)%8==7
                    g_hloc[((size_t)((s + 3) >> 3) * B_ + b) * G_ + u] = hn;
            }
            q[i] = qn;
            __syncthreads();
        }
    }
}

// ---------------------------------------------------------------------------
// Output projection: out[b][n][p] = h_loc[n][b][:] . Wp[:,p] + bp[p]
__global__ void proj_kernel(const float* __restrict__ Wp, const float* __restrict__ bp,
                            float* __restrict__ out)
{
    int gw   = (blockIdx.x * blockDim.x + threadIdx.x) >> 5;
    int lane = threadIdx.x & 31;
    if (gw >= B_ * N_) return;
    int b = gw / N_, n = gw % N_;
    if (lane < PW_) {
        const float* hl = g_hloc + ((size_t)n * B_ + b) * G_;
        float acc = bp[lane];
#pragma unroll
        for (int g = 0; g < G_; g++) acc = fmaf(hl[g], Wp[g * PW_ + lane], acc);
        out[((size_t)b * N_ + n) * PW_ + lane] = acc;
    }
}

// ---------------------------------------------------------------------------
extern "C" void kernel_launch(void* const* d_in, const int* in_sizes, int n_in,
                              void* d_out, int out_size)
{
    const float* dynamic = (const float*)d_in[0];
    const float* h0      = (const float*)d_in[1];
    const int*   src     = (const int*)  d_in[2];
    const float* W1      = (const float*)d_in[3];
    const float* b1      = (const float*)d_in[4];
    const float* a1      = (const float*)d_in[5];
    const float* a1b     = (const float*)d_in[6];
    const float* W2      = (const float*)d_in[7];
    const float* b2      = (const float*)d_in[8];
    const float* a2      = (const float*)d_in[9];
    const float* a2b     = (const float*)d_in[10];
    const float* Wih     = (const float*)d_in[11];
    const float* Whh     = (const float*)d_in[12];
    const float* bih     = (const float*)d_in[13];
    const float* bhh     = (const float*)d_in[14];
    const float* Wp      = (const float*)d_in[15];
    const float* bp      = (const float*)d_in[16];
    float* out = (float*)d_out;

    float *z1p, *h1p, *z2p, *seqTp, *gip, *W1catp, *WihTp;
    cudaGetSymbolAddress((void**)&z1p,    g_z1);
    cudaGetSymbolAddress((void**)&h1p,    g_h1);
    cudaGetSymbolAddress((void**)&z2p,    g_z2);
    cudaGetSymbolAddress((void**)&seqTp,  g_seqT);
    cudaGetSymbolAddress((void**)&gip,    g_gi);
    cudaGetSymbolAddress((void**)&W1catp, g_W1cat);
    cudaGetSymbolAddress((void**)&WihTp,  g_WihT);

    // 0) pack weights
    pack_kernel<<<128, 256>>>(W1, Wih);

    // 1) z1 = x @ W1cat + b1   (per (b,t): 2000x128 @ 128x256)
    gemm_bias<<<dim3(16, 4, BT_), 256>>>(dynamic, W1catp, b1, z1p,
                                         N_, HD_, F_, T_ * F_, HD_,
                                         (long)N_ * T_ * F_, (long)F_, T_,
                                         (long)N_ * HD_);
    // 2) attention scores + aggregation layer 1 -> h1 (ELU)
    scores1_kernel<<<16000, 256>>>(a1);
    attn1_kernel<<<16000, 256>>>(src, a1b);

    // 3) z2 = h1 @ W2 + b2   (per (b,t): 2000x256 @ 256x64)
    gemm_bias<<<dim3(16, 1, BT_), 256>>>(h1p, W2, b2, z2p,
                                         N_, D2_, HD_, HD_, D2_,
                                         (long)N_ * HD_, 0L, 1,
                                         (long)N_ * D2_);
    // 4) attention layer 2 -> seqT (xs layout), ELU
    scores2_kernel<<<16000, 256>>>(a2);
    attn2_kernel<<<16000, 256>>>(src, a2b);

    // 5) gi = seqT @ WihT + bih   (128000x64 @ 64x192)
    gemm_bias<<<dim3(1000, 3, 1), 256>>>(seqTp, WihTp, bih, gip,
                                         SEQ_ * B_, 3 * G_, D2_, D2_, 3 * G_,
                                         0L, 0L, 1, 0L);

    // 6) sequential GRU scan (8 independent chains) — v2: 1 bar/step, f32x2
    gru_scan<<<B_, 256>>>(gip, h0, Whh, bhh);

    // 7) projection
    proj_kernel<<<2000, 256>>>(Wp, bp, out);
}